// round 4
// baseline (speedup 1.0000x reference)
#include <cuda_runtime.h>

#define NPTS   4096
#define NPROB  3
#define NSTEPS 11
#define LOGN   8.317766166719343f     /* ln(4096) */
#define LN2    0.6931471805599453f
#define LOG2E  1.4426950408889634f

// potentials and packed column data live in device globals (no allocation allowed)
__device__ float  d_fpot[NPROB][NPTS];
__device__ float  d_gpot[NPROB][NPTS];
__device__ float4 d_pack[NPROB][NPTS];

__device__ __forceinline__ float ex2f(float v) {
    float r; asm("ex2.approx.f32 %0, %1;" : "=f"(r) : "f"(v)); return r;
}
__device__ __forceinline__ float lg2f(float v) {
    float r; asm("lg2.approx.f32 %0, %1;" : "=f"(r) : "f"(v)); return r;
}

__global__ void zero_pot() {
    int i = blockIdx.x * blockDim.x + threadIdx.x;
    if (i < NPROB * NPTS) {
        (&d_fpot[0][0])[i] = 0.f;
        (&d_gpot[0][0])[i] = 0.f;
    }
}

// Build packed column array for one half-step.
// phase 0 (f-update): columns are B-side points with potential g
// phase 1 (g-update): columns are A-side points with potential f (freshly updated)
// pack[j] = { b_j * s, (q_j - 0.5|b_j|^2) * s },  s = log2(e)/eps
__global__ void prep(const float* __restrict__ x, const float* __restrict__ y,
                     float scale, int phase) {
    int j = blockIdx.x * blockDim.x + threadIdx.x;
    int p = blockIdx.y;
    // problems: 0:(A=x,B=y)  1:(A=x,B=x)  2:(A=y,B=y)
    const float* Apts = (p == 2) ? y : x;
    const float* Bpts = (p == 1) ? x : y;
    const float* cpts = phase ? Apts : Bpts;
    const float* q    = phase ? d_fpot[p] : d_gpot[p];

    float cx = cpts[3 * j], cy = cpts[3 * j + 1], cz = cpts[3 * j + 2];
    float hs = 0.5f * (cx * cx + cy * cy + cz * cz);
    d_pack[p][j] = make_float4(cx * scale, cy * scale, cz * scale, (q[j] - hs) * scale);
}

// One half-step: out_i = eps*ln(N) + 0.5|p_i|^2 - eps*ln2 * log2( sum_j 2^{w_ij} )
// with w_ij = pack.w_j + p_i . pack.xyz_j   (everything pre-scaled into base-2/eps units)
// Block = 128 threads (4 warps). Each warp owns 4 rows; lanes stride over columns.
__global__ void __launch_bounds__(128) half_step(const float* __restrict__ x,
                                                 const float* __restrict__ y,
                                                 float eps, int phase) {
    int p = blockIdx.y;
    const float* Apts = (p == 2) ? y : x;
    const float* Bpts = (p == 1) ? x : y;
    const float* rpts = phase ? Bpts : Apts;          // row points
    float*       out  = phase ? d_gpot[p] : d_fpot[p];
    const float4* __restrict__ cols = d_pack[p];

    int warp = threadIdx.x >> 5, lane = threadIdx.x & 31;
    int row0 = (blockIdx.x * 4 + warp) * 4;           // 16 rows per block

    float ax[4], ay[4], az[4], m[4], s[4];
#pragma unroll
    for (int t = 0; t < 4; t++) {
        int r = row0 + t;
        ax[t] = rpts[3 * r]; ay[t] = rpts[3 * r + 1]; az[t] = rpts[3 * r + 2];
        m[t] = -1e30f; s[t] = 0.f;
    }

#pragma unroll 4
    for (int j = lane; j < NPTS; j += 32) {
        float4 c = cols[j];
#pragma unroll
        for (int t = 0; t < 4; t++) {
            float w = fmaf(ax[t], c.x, fmaf(ay[t], c.y, fmaf(az[t], c.z, c.w)));
            // branchless online logsumexp: exactly one ex2 per element
            float d = w - m[t];
            float e = ex2f(-fabsf(d));        // -|d| is a free operand modifier
            m[t] = fmaxf(m[t], w);
            s[t] = (d > 0.f) ? fmaf(s[t], e, 1.f) : (s[t] + e);
        }
    }

    // warp-level logsumexp merge
#pragma unroll
    for (int t = 0; t < 4; t++) {
#pragma unroll
        for (int off = 16; off; off >>= 1) {
            float m2 = __shfl_down_sync(0xffffffffu, m[t], off);
            float s2 = __shfl_down_sync(0xffffffffu, s[t], off);
            float nm = fmaxf(m[t], m2);
            s[t] = fmaf(s[t], ex2f(m[t] - nm), s2 * ex2f(m2 - nm));
            m[t] = nm;
        }
    }

    if (lane == 0) {
#pragma unroll
        for (int t = 0; t < 4; t++) {
            int r = row0 + t;
            float hs = 0.5f * (ax[t] * ax[t] + ay[t] * ay[t] + az[t] * az[t]);
            out[r] = fmaf(eps, LOGN, hs) - eps * LN2 * (m[t] + lg2f(s[t]));
        }
    }
}

// result = (mean f0 + mean g0) - 0.5*(mean f1 + mean g1) - 0.5*(mean f2 + mean g2)
__global__ void finalize(float* __restrict__ outp) {
    __shared__ double sh[256];
    int t = threadIdx.x;
    double acc = 0.0;
    for (int p = 0; p < NPROB; p++) {
        double cp = (p == 0) ? 1.0 : -0.5;
        for (int i = t; i < NPTS; i += 256)
            acc += cp * ((double)d_fpot[p][i] + (double)d_gpot[p][i]);
    }
    sh[t] = acc;
    __syncthreads();
    for (int st = 128; st; st >>= 1) {
        if (t < st) sh[t] += sh[t + st];
        __syncthreads();
    }
    if (t == 0) outp[0] = (float)(sh[0] / (double)NPTS);
}

extern "C" void kernel_launch(void* const* d_in, const int* in_sizes, int n_in,
                              void* d_out, int out_size) {
    const float* x = (const float*)d_in[0];
    const float* y = (const float*)d_in[1];
    float* out = (float*)d_out;

    static const float eps_sched[NSTEPS] = {
        4.0f, 1.0f, 0.25f, 0.0625f, 0.015625f, 0.00390625f,
        0.0025f, 0.0025f, 0.0025f, 0.0025f, 0.0025f
    };

    zero_pot<<<(NPROB * NPTS + 255) / 256, 256>>>();

    for (int it = 0; it < NSTEPS; ++it) {
        float eps = eps_sched[it];
        float sc = LOG2E / eps;
        // f-update: rows = A points, cols = B points with g
        prep<<<dim3(NPTS / 256, NPROB), 256>>>(x, y, sc, 0);
        half_step<<<dim3(NPTS / 16, NPROB), 128>>>(x, y, eps, 0);
        // g-update: rows = B points, cols = A points with (new) f
        prep<<<dim3(NPTS / 256, NPROB), 256>>>(x, y, sc, 1);
        half_step<<<dim3(NPTS / 16, NPROB), 128>>>(x, y, eps, 1);
    }

    finalize<<<1, 256>>>(out);
}

// round 8
// speedup vs baseline: 1.0677x; 1.0677x over previous
#include <cuda_runtime.h>

#define NPTS   4096
#define NPROB  3
#define NSTEPS 11
#define LOGN   8.317766166719343f     /* ln(4096) */
#define LN2    0.6931471805599453f
#define LOG2E  1.4426950408889634f

// Device-global state (no allocation allowed).
// d_pack is double-buffered: phase 0 reads buf0 / writes buf1, phase 1 reads buf1 / writes buf0.
__device__ float  d_fpot[NPROB][NPTS];
__device__ float  d_gpot[NPROB][NPTS];
__device__ float4 d_pack[2][NPROB][NPTS];

__device__ __forceinline__ float ex2f(float v) {
    float r; asm("ex2.approx.f32 %0, %1;" : "=f"(r) : "f"(v)); return r;
}
__device__ __forceinline__ float lg2f(float v) {
    float r; asm("lg2.approx.f32 %0, %1;" : "=f"(r) : "f"(v)); return r;
}

// Seed pack buffer 0 for the first f-update: columns = B-side points, g = 0.
// pack[j] = { b_j * s, (0 - 0.5|b_j|^2) * s },  s = log2(e)/eps0
__global__ void init_pack(const float* __restrict__ x, const float* __restrict__ y,
                          float sc0) {
    int j = blockIdx.x * blockDim.x + threadIdx.x;
    int p = blockIdx.y;
    // problems: 0:(A=x,B=y)  1:(A=x,B=x)  2:(A=y,B=y)
    const float* Bpts = (p == 1) ? x : y;
    float cx = Bpts[3 * j], cy = Bpts[3 * j + 1], cz = Bpts[3 * j + 2];
    float hs = 0.5f * (cx * cx + cy * cy + cz * cz);
    d_pack[0][p][j] = make_float4(cx * sc0, cy * sc0, cz * sc0, -hs * sc0);
}

// One half-step, fused with pack construction for the NEXT half-step.
//   out_i = eps*ln(N) + 0.5|p_i|^2 - eps*ln2 * log2( sum_j 2^{w_ij} )
//   w_ij  = pack_in.w_j + p_i . pack_in.xyz_j   (pre-scaled base-2/eps units)
// Epilogue: pack_out[i] = { p_i * sc_out, (out_i - 0.5|p_i|^2) * sc_out }
//   phase 0 (f-update): rows = A pts, sc_out uses SAME eps (feeds g-update)
//   phase 1 (g-update): rows = B pts, sc_out uses NEXT iteration's eps (feeds next f-update)
// Block = 128 threads (4 warps). Each warp owns 4 rows; lanes stride over columns.
__global__ void __launch_bounds__(128) half_step(const float* __restrict__ x,
                                                 const float* __restrict__ y,
                                                 float eps, float sc_out, int phase) {
    int p = blockIdx.y;
    const float* Apts = (p == 2) ? y : x;
    const float* Bpts = (p == 1) ? x : y;
    const float* rpts = phase ? Bpts : Apts;          // row points
    float*       out  = phase ? d_gpot[p] : d_fpot[p];
    const float4* __restrict__ cols     = d_pack[phase][p];
    float4*       __restrict__ pack_out = d_pack[phase ^ 1][p];

    int warp = threadIdx.x >> 5, lane = threadIdx.x & 31;
    int row0 = (blockIdx.x * 4 + warp) * 4;           // 16 rows per block

    float ax[4], ay[4], az[4], m[4], s[4];
#pragma unroll
    for (int t = 0; t < 4; t++) {
        int r = row0 + t;
        ax[t] = rpts[3 * r]; ay[t] = rpts[3 * r + 1]; az[t] = rpts[3 * r + 2];
        m[t] = -1e30f; s[t] = 0.f;
    }

#pragma unroll 4
    for (int j = lane; j < NPTS; j += 32) {
        float4 c = cols[j];
#pragma unroll
        for (int t = 0; t < 4; t++) {
            float w = fmaf(ax[t], c.x, fmaf(ay[t], c.y, fmaf(az[t], c.z, c.w)));
            // branchless online logsumexp: exactly one ex2 per element
            float d = w - m[t];
            float e = ex2f(-fabsf(d));        // -|d| is a free operand modifier
            m[t] = fmaxf(m[t], w);
            s[t] = (d > 0.f) ? fmaf(s[t], e, 1.f) : (s[t] + e);
        }
    }

    // warp-level logsumexp merge
#pragma unroll
    for (int t = 0; t < 4; t++) {
#pragma unroll
        for (int off = 16; off; off >>= 1) {
            float m2 = __shfl_down_sync(0xffffffffu, m[t], off);
            float s2 = __shfl_down_sync(0xffffffffu, s[t], off);
            float nm = fmaxf(m[t], m2);
            s[t] = fmaf(s[t], ex2f(m[t] - nm), s2 * ex2f(m2 - nm));
            m[t] = nm;
        }
    }

    if (lane == 0) {
#pragma unroll
        for (int t = 0; t < 4; t++) {
            int r = row0 + t;
            float hs = 0.5f * (ax[t] * ax[t] + ay[t] * ay[t] + az[t] * az[t]);
            float pot = fmaf(eps, LOGN, hs) - eps * LN2 * (m[t] + lg2f(s[t]));
            out[r] = pot;
            pack_out[r] = make_float4(ax[t] * sc_out, ay[t] * sc_out,
                                      az[t] * sc_out, (pot - hs) * sc_out);
        }
    }
}

// result = (mean f0 + mean g0) - 0.5*(mean f1 + mean g1) - 0.5*(mean f2 + mean g2)
__global__ void finalize(float* __restrict__ outp) {
    __shared__ double sh[256];
    int t = threadIdx.x;
    double acc = 0.0;
    for (int p = 0; p < NPROB; p++) {
        double cp = (p == 0) ? 1.0 : -0.5;
        for (int i = t; i < NPTS; i += 256)
            acc += cp * ((double)d_fpot[p][i] + (double)d_gpot[p][i]);
    }
    sh[t] = acc;
    __syncthreads();
    for (int st = 128; st; st >>= 1) {
        if (t < st) sh[t] += sh[t + st];
        __syncthreads();
    }
    if (t == 0) outp[0] = (float)(sh[0] / (double)NPTS);
}

extern "C" void kernel_launch(void* const* d_in, const int* in_sizes, int n_in,
                              void* d_out, int out_size) {
    const float* x = (const float*)d_in[0];
    const float* y = (const float*)d_in[1];
    float* out = (float*)d_out;

    static const float eps_sched[NSTEPS] = {
        4.0f, 1.0f, 0.25f, 0.0625f, 0.015625f, 0.00390625f,
        0.0025f, 0.0025f, 0.0025f, 0.0025f, 0.0025f
    };

    init_pack<<<dim3(NPTS / 256, NPROB), 256>>>(x, y, LOG2E / eps_sched[0]);

    for (int it = 0; it < NSTEPS; ++it) {
        float eps = eps_sched[it];
        float sc_cur  = LOG2E / eps;
        float sc_next = LOG2E / eps_sched[(it + 1 < NSTEPS) ? it + 1 : it];
        // f-update: rows = A, reads buf0 (B/g), writes buf1 (A/f) at current eps
        half_step<<<dim3(NPTS / 16, NPROB), 128>>>(x, y, eps, sc_cur, 0);
        // g-update: rows = B, reads buf1 (A/f), writes buf0 (B/g) at NEXT eps
        half_step<<<dim3(NPTS / 16, NPROB), 128>>>(x, y, eps, sc_next, 1);
    }

    finalize<<<1, 256>>>(out);
}

// round 9
// speedup vs baseline: 1.2381x; 1.1596x over previous
#include <cuda_runtime.h>

#define NPTS   4096
#define NPROB  3
#define NSTEPS 11
#define LOGN   8.317766166719343f     /* ln(4096) */
#define LN2    0.6931471805599453f
#define LOG2E  1.4426950408889634f

// Device-global state (no allocation allowed).
// d_pack is double-buffered: phase 0 reads buf0 / writes buf1, phase 1 reads buf1 / writes buf0.
__device__ float  d_fpot[NPROB][NPTS];
__device__ float  d_gpot[NPROB][NPTS];
__device__ float4 d_pack[2][NPROB][NPTS];

__device__ __forceinline__ float ex2f(float v) {
    float r; asm("ex2.approx.f32 %0, %1;" : "=f"(r) : "f"(v)); return r;
}
__device__ __forceinline__ float lg2f(float v) {
    float r; asm("lg2.approx.f32 %0, %1;" : "=f"(r) : "f"(v)); return r;
}

// Seed pack buffer 0 for the first f-update: columns = B-side points, g = 0.
// pack[j] = { b_j * s, (0 - 0.5|b_j|^2) * s },  s = log2(e)/eps0
__global__ void init_pack(const float* __restrict__ x, const float* __restrict__ y,
                          float sc0) {
    int j = blockIdx.x * blockDim.x + threadIdx.x;
    int p = blockIdx.y;
    // problems: 0:(A=x,B=y)  1:(A=x,B=x)  2:(A=y,B=y)
    const float* Bpts = (p == 1) ? x : y;
    float cx = Bpts[3 * j], cy = Bpts[3 * j + 1], cz = Bpts[3 * j + 2];
    float hs = 0.5f * (cx * cx + cy * cy + cz * cz);
    d_pack[0][p][j] = make_float4(cx * sc0, cy * sc0, cz * sc0, -hs * sc0);
}

// One half-step, fused with pack construction for the NEXT half-step.
//   out_i = eps*ln(N) + 0.5|p_i|^2 - eps*ln2 * log2( sum_j 2^{w_ij} )
//   w_ij  = pack_in.w_j + p_i . pack_in.xyz_j   (pre-scaled base-2/eps units)
// Epilogue: pack_out[i] = { p_i * sc_out, (out_i - 0.5|p_i|^2) * sc_out }
// Block = 128 threads (4 warps). Each warp owns TWO rows (occupancy: 6144 warps
// total ≈ 42/SM, vs 21/SM with 4 rows/warp which profiled latency-bound at
// issue=53.8%, occ=30%). Lanes stride over columns.
__global__ void __launch_bounds__(128) half_step(const float* __restrict__ x,
                                                 const float* __restrict__ y,
                                                 float eps, float sc_out, int phase) {
    int p = blockIdx.y;
    const float* Apts = (p == 2) ? y : x;
    const float* Bpts = (p == 1) ? x : y;
    const float* rpts = phase ? Bpts : Apts;          // row points
    float*       out  = phase ? d_gpot[p] : d_fpot[p];
    const float4* __restrict__ cols     = d_pack[phase][p];
    float4*       __restrict__ pack_out = d_pack[phase ^ 1][p];

    int warp = threadIdx.x >> 5, lane = threadIdx.x & 31;
    int row0 = (blockIdx.x * 4 + warp) * 2;           // 8 rows per block

    float ax[2], ay[2], az[2], m[2], s[2];
#pragma unroll
    for (int t = 0; t < 2; t++) {
        int r = row0 + t;
        ax[t] = rpts[3 * r]; ay[t] = rpts[3 * r + 1]; az[t] = rpts[3 * r + 2];
        m[t] = -1e30f; s[t] = 0.f;
    }

#pragma unroll 4
    for (int j = lane; j < NPTS; j += 32) {
        float4 c = cols[j];
#pragma unroll
        for (int t = 0; t < 2; t++) {
            float w = fmaf(ax[t], c.x, fmaf(ay[t], c.y, fmaf(az[t], c.z, c.w)));
            // branchless online logsumexp: exactly one ex2 per element
            float d = w - m[t];
            float e = ex2f(-fabsf(d));        // -|d| is a free operand modifier
            m[t] = fmaxf(m[t], w);
            s[t] = (d > 0.f) ? fmaf(s[t], e, 1.f) : (s[t] + e);
        }
    }

    // warp-level logsumexp merge
#pragma unroll
    for (int t = 0; t < 2; t++) {
#pragma unroll
        for (int off = 16; off; off >>= 1) {
            float m2 = __shfl_down_sync(0xffffffffu, m[t], off);
            float s2 = __shfl_down_sync(0xffffffffu, s[t], off);
            float nm = fmaxf(m[t], m2);
            s[t] = fmaf(s[t], ex2f(m[t] - nm), s2 * ex2f(m2 - nm));
            m[t] = nm;
        }
    }

    if (lane == 0) {
#pragma unroll
        for (int t = 0; t < 2; t++) {
            int r = row0 + t;
            float hs = 0.5f * (ax[t] * ax[t] + ay[t] * ay[t] + az[t] * az[t]);
            float pot = fmaf(eps, LOGN, hs) - eps * LN2 * (m[t] + lg2f(s[t]));
            out[r] = pot;
            pack_out[r] = make_float4(ax[t] * sc_out, ay[t] * sc_out,
                                      az[t] * sc_out, (pot - hs) * sc_out);
        }
    }
}

// result = (mean f0 + mean g0) - 0.5*(mean f1 + mean g1) - 0.5*(mean f2 + mean g2)
__global__ void finalize(float* __restrict__ outp) {
    __shared__ double sh[256];
    int t = threadIdx.x;
    double acc = 0.0;
    for (int p = 0; p < NPROB; p++) {
        double cp = (p == 0) ? 1.0 : -0.5;
        for (int i = t; i < NPTS; i += 256)
            acc += cp * ((double)d_fpot[p][i] + (double)d_gpot[p][i]);
    }
    sh[t] = acc;
    __syncthreads();
    for (int st = 128; st; st >>= 1) {
        if (t < st) sh[t] += sh[t + st];
        __syncthreads();
    }
    if (t == 0) outp[0] = (float)(sh[0] / (double)NPTS);
}

extern "C" void kernel_launch(void* const* d_in, const int* in_sizes, int n_in,
                              void* d_out, int out_size) {
    const float* x = (const float*)d_in[0];
    const float* y = (const float*)d_in[1];
    float* out = (float*)d_out;

    static const float eps_sched[NSTEPS] = {
        4.0f, 1.0f, 0.25f, 0.0625f, 0.015625f, 0.00390625f,
        0.0025f, 0.0025f, 0.0025f, 0.0025f, 0.0025f
    };

    init_pack<<<dim3(NPTS / 256, NPROB), 256>>>(x, y, LOG2E / eps_sched[0]);

    for (int it = 0; it < NSTEPS; ++it) {
        float eps = eps_sched[it];
        float sc_cur  = LOG2E / eps;
        float sc_next = LOG2E / eps_sched[(it + 1 < NSTEPS) ? it + 1 : it];
        // f-update: rows = A, reads buf0 (B/g), writes buf1 (A/f) at current eps
        half_step<<<dim3(NPTS / 8, NPROB), 128>>>(x, y, eps, sc_cur, 0);
        // g-update: rows = B, reads buf1 (A/f), writes buf0 (B/g) at NEXT eps
        half_step<<<dim3(NPTS / 8, NPROB), 128>>>(x, y, eps, sc_next, 1);
    }

    finalize<<<1, 256>>>(out);
}

// round 15
// speedup vs baseline: 1.4441x; 1.1664x over previous
#include <cuda_runtime.h>

#define NPTS   4096
#define NPROB  3
#define NSTEPS 11
#define LOGN   8.317766166719343f     /* ln(4096) */
#define LN2    0.6931471805599453f
#define LOG2E  1.4426950408889634f

// Device-global state (no allocation allowed).
// d_pack is double-buffered: phase 0 reads buf0 / writes buf1, phase 1 reads buf1 / writes buf0.
__device__ float  d_fpot[NPROB][NPTS];
__device__ float  d_gpot[NPROB][NPTS];
__device__ float4 d_pack[2][NPROB][NPTS];

__device__ __forceinline__ float ex2f(float v) {
    float r; asm("ex2.approx.f32 %0, %1;" : "=f"(r) : "f"(v)); return r;
}
__device__ __forceinline__ float lg2f(float v) {
    float r; asm("lg2.approx.f32 %0, %1;" : "=f"(r) : "f"(v)); return r;
}

// Seed pack buffer 0 for the first f-update: columns = B-side points, g = 0.
// pack[j] = { b_j * s, (0 - 0.5|b_j|^2) * s },  s = log2(e)/eps0
__global__ void init_pack(const float* __restrict__ x, const float* __restrict__ y,
                          float sc0) {
    int j = blockIdx.x * blockDim.x + threadIdx.x;
    int p = blockIdx.y;
    // problems: 0:(A=x,B=y)  1:(A=x,B=x)  2:(A=y,B=y)
    const float* Bpts = (p == 1) ? x : y;
    float cx = Bpts[3 * j], cy = Bpts[3 * j + 1], cz = Bpts[3 * j + 2];
    float hs = 0.5f * (cx * cx + cy * cy + cz * cz);
    d_pack[0][p][j] = make_float4(cx * sc0, cy * sc0, cz * sc0, -hs * sc0);
}

// One half-step, fused with pack construction for the NEXT half-step.
//   out_i = eps*ln(N) + 0.5|p_i|^2 - eps*ln2 * log2( sum_j 2^{w_ij} )
//   w_ij  = pack_in.w_j + p_i . pack_in.xyz_j   (pre-scaled base-2/eps units)
// Epilogue: pack_out[i] = { p_i * sc_out, (out_i - 0.5|p_i|^2) * sc_out }
//
// Inner loop: chunked two-phase logsumexp over 4-column chunks. Exact algebra:
//   mn = max(m, w0..w3);  s = s*2^(m-mn) + sum_k 2^(w_k-mn);  m = mn
// (all shifted exponents <= 0, no overflow; first chunk: 2^(-1e30-mn)=0).
// This removes the per-element FSETP+select chain of the online variant:
// ~8.2 issue slots/element vs ~10.5 (round-9 profile was issue-bound at 84.8%).
// Block = 128 threads (4 warps); each warp owns 2 rows; lanes stride columns.
__global__ void __launch_bounds__(128) half_step(const float* __restrict__ x,
                                                 const float* __restrict__ y,
                                                 float eps, float sc_out, int phase) {
    int p = blockIdx.y;
    const float* Apts = (p == 2) ? y : x;
    const float* Bpts = (p == 1) ? x : y;
    const float* rpts = phase ? Bpts : Apts;          // row points
    float*       out  = phase ? d_gpot[p] : d_fpot[p];
    const float4* __restrict__ cols     = d_pack[phase][p];
    float4*       __restrict__ pack_out = d_pack[phase ^ 1][p];

    int warp = threadIdx.x >> 5, lane = threadIdx.x & 31;
    int row0 = (blockIdx.x * 4 + warp) * 2;           // 8 rows per block

    float ax[2], ay[2], az[2], m[2], s[2];
#pragma unroll
    for (int t = 0; t < 2; t++) {
        int r = row0 + t;
        ax[t] = rpts[3 * r]; ay[t] = rpts[3 * r + 1]; az[t] = rpts[3 * r + 2];
        m[t] = -1e30f; s[t] = 0.f;
    }

    const float4* __restrict__ colp = cols + lane;
#pragma unroll 2
    for (int chunk = 0; chunk < NPTS / (32 * 4); chunk++) {
        float4 c0 = colp[0], c1 = colp[32], c2 = colp[64], c3 = colp[96];
#pragma unroll
        for (int t = 0; t < 2; t++) {
            float w0 = fmaf(ax[t], c0.x, fmaf(ay[t], c0.y, fmaf(az[t], c0.z, c0.w)));
            float w1 = fmaf(ax[t], c1.x, fmaf(ay[t], c1.y, fmaf(az[t], c1.z, c1.w)));
            float w2 = fmaf(ax[t], c2.x, fmaf(ay[t], c2.y, fmaf(az[t], c2.z, c2.w)));
            float w3 = fmaf(ax[t], c3.x, fmaf(ay[t], c3.y, fmaf(az[t], c3.z, c3.w)));
            float mc = fmaxf(fmaxf(w0, w1), fmaxf(w2, w3));
            float mn = fmaxf(m[t], mc);
            float e0 = ex2f(w0 - mn) + ex2f(w1 - mn);
            float e1 = ex2f(w2 - mn) + ex2f(w3 - mn);
            s[t] = fmaf(s[t], ex2f(m[t] - mn), e0 + e1);
            m[t] = mn;
        }
        colp += 128;
    }

    // warp-level logsumexp merge
#pragma unroll
    for (int t = 0; t < 2; t++) {
#pragma unroll
        for (int off = 16; off; off >>= 1) {
            float m2 = __shfl_down_sync(0xffffffffu, m[t], off);
            float s2 = __shfl_down_sync(0xffffffffu, s[t], off);
            float nm = fmaxf(m[t], m2);
            s[t] = fmaf(s[t], ex2f(m[t] - nm), s2 * ex2f(m2 - nm));
            m[t] = nm;
        }
    }

    if (lane == 0) {
#pragma unroll
        for (int t = 0; t < 2; t++) {
            int r = row0 + t;
            float hs = 0.5f * (ax[t] * ax[t] + ay[t] * ay[t] + az[t] * az[t]);
            float pot = fmaf(eps, LOGN, hs) - eps * LN2 * (m[t] + lg2f(s[t]));
            out[r] = pot;
            pack_out[r] = make_float4(ax[t] * sc_out, ay[t] * sc_out,
                                      az[t] * sc_out, (pot - hs) * sc_out);
        }
    }
}

// result = (mean f0 + mean g0) - 0.5*(mean f1 + mean g1) - 0.5*(mean f2 + mean g2)
__global__ void finalize(float* __restrict__ outp) {
    __shared__ double sh[256];
    int t = threadIdx.x;
    double acc = 0.0;
    for (int p = 0; p < NPROB; p++) {
        double cp = (p == 0) ? 1.0 : -0.5;
        for (int i = t; i < NPTS; i += 256)
            acc += cp * ((double)d_fpot[p][i] + (double)d_gpot[p][i]);
    }
    sh[t] = acc;
    __syncthreads();
    for (int st = 128; st; st >>= 1) {
        if (t < st) sh[t] += sh[t + st];
        __syncthreads();
    }
    if (t == 0) outp[0] = (float)(sh[0] / (double)NPTS);
}

extern "C" void kernel_launch(void* const* d_in, const int* in_sizes, int n_in,
                              void* d_out, int out_size) {
    const float* x = (const float*)d_in[0];
    const float* y = (const float*)d_in[1];
    float* out = (float*)d_out;

    static const float eps_sched[NSTEPS] = {
        4.0f, 1.0f, 0.25f, 0.0625f, 0.015625f, 0.00390625f,
        0.0025f, 0.0025f, 0.0025f, 0.0025f, 0.0025f
    };

    init_pack<<<dim3(NPTS / 256, NPROB), 256>>>(x, y, LOG2E / eps_sched[0]);

    for (int it = 0; it < NSTEPS; ++it) {
        float eps = eps_sched[it];
        float sc_cur  = LOG2E / eps;
        float sc_next = LOG2E / eps_sched[(it + 1 < NSTEPS) ? it + 1 : it];
        // f-update: rows = A, reads buf0 (B/g), writes buf1 (A/f) at current eps
        half_step<<<dim3(NPTS / 8, NPROB), 128>>>(x, y, eps, sc_cur, 0);
        // g-update: rows = B, reads buf1 (A/f), writes buf0 (B/g) at NEXT eps
        half_step<<<dim3(NPTS / 8, NPROB), 128>>>(x, y, eps, sc_next, 1);
    }

    finalize<<<1, 256>>>(out);
}